// round 12
// baseline (speedup 1.0000x reference)
#include <cuda_runtime.h>
#include <cuda_fp16.h>
#include <cuda_bf16.h>
#include <cstdint>

// ---------------------------------------------------------------------------
// GCN layer, reordered:  out = A @ (x @ W) + bias
//   Kernel A (fused): blocks [0,G1)  : xw = x @ W  (tf32 mma, cp.async 2-stage,
//                                      fp32 accum, fp16 store)
//                     blocks [G1,..) : CSR row_ptr from sorted COO rows
//   Kernel B: out = A @ xw + bias    (CSR SpMM, warp/node; 2 edges per
//                                     LDG.128, half-warp per edge, fp32 accum)
// ---------------------------------------------------------------------------

#define D 128
#define MAX_NODES 100000

__device__ __half g_xw[(size_t)MAX_NODES * D];   // fp16: halves gather traffic
__device__ int    g_row_ptr[MAX_NODES + 1];

__device__ __forceinline__ uint32_t f2tf32(float f) {
    uint32_t r;
    asm("cvt.rna.tf32.f32 %0, %1;" : "=r"(r) : "f"(f));
    return r;
}

__device__ __forceinline__ void mma16n8k8(float* c, const uint32_t* a,
                                          uint32_t b0, uint32_t b1) {
    asm volatile(
        "mma.sync.aligned.m16n8k8.row.col.f32.tf32.tf32.f32 "
        "{%0,%1,%2,%3}, {%4,%5,%6,%7}, {%8,%9}, {%0,%1,%2,%3};"
        : "+f"(c[0]), "+f"(c[1]), "+f"(c[2]), "+f"(c[3])
        : "r"(a[0]), "r"(a[1]), "r"(a[2]), "r"(a[3]), "r"(b0), "r"(b1));
}

__device__ __forceinline__ void cp_async16(void* smem_dst, const void* gsrc, int src_bytes) {
    uint32_t sa = (uint32_t)__cvta_generic_to_shared(smem_dst);
    asm volatile("cp.async.cg.shared.global [%0], [%1], 16, %2;\n"
                 :: "r"(sa), "l"(gsrc), "r"(src_bytes));
}
__device__ __forceinline__ void cp_async_commit() {
    asm volatile("cp.async.commit_group;\n");
}
template <int NG>
__device__ __forceinline__ void cp_async_wait() {
    asm volatile("cp.async.wait_group %0;\n" :: "n"(NG));
}

// Dynamic smem layout (floats):
//   AS(st, r, c) : 2 x [128][36]  at offset st*4608 + r*36 + c
//   WS(st, r, c) : 2 x [32][136]  at offset 9216 + st*4352 + r*136 + c
#define AS_OFF(st, r, c) ((st) * 4608 + (r) * 36 + (c))
#define WS_OFF(st, r, c) (9216 + (st) * 4352 + (r) * 136 + (c))
#define SMEM_FLOATS (9216 + 2 * 4352)

// ---------------------------------------------------------------------------
// Fused kernel: GEMM blocks + row_ptr blocks (independent work, one launch)
// ---------------------------------------------------------------------------
__global__ void __launch_bounds__(256) fused_gemm_rowptr_kernel(
    const float* __restrict__ x,     // [M, 128]
    const float* __restrict__ Wm,    // [128, 128]
    const int*   __restrict__ erow,  // [E] sorted
    int M, int N, int E, int G1)
{
    extern __shared__ float sm[];
    const int tid = threadIdx.x;

    if (blockIdx.x >= G1) {
        // ----- row_ptr part: 16 edges per thread (4x int4) -----
        const int t    = (blockIdx.x - G1) * 256 + tid;
        const int base = t * 16;
        if (base >= E) return;

        int v[17];
        v[0] = (base == 0) ? -1 : erow[base - 1];

        const int cnt = min(16, E - base);
        if (cnt == 16) {
            #pragma unroll
            for (int q = 0; q < 4; q++) {
                const int4 a = *(const int4*)(erow + base + q * 4);
                v[q * 4 + 1] = a.x; v[q * 4 + 2] = a.y;
                v[q * 4 + 3] = a.z; v[q * 4 + 4] = a.w;
            }
        } else {
            for (int k = 0; k < cnt; k++) v[k + 1] = erow[base + k];
        }

        #pragma unroll
        for (int k = 1; k <= 16; k++) {
            if (k <= cnt) {
                for (int r = v[k - 1] + 1; r <= v[k]; r++)
                    g_row_ptr[r] = base + k - 1;
            }
        }
        if (base + cnt == E) {
            for (int r = v[cnt] + 1; r <= N; r++) g_row_ptr[r] = E;
        }
        return;
    }

    // ----- GEMM part: 128x128 tile, 2-stage cp.async pipeline -----
    const int lane = tid & 31;
    const int wid  = tid >> 5;
    const int wm   = wid & 3;
    const int wn   = wid >> 2;
    const int row0 = blockIdx.x * 128;

    const int gID = lane >> 2;
    const int tig = lane & 3;

    int a_row[4], a_seg[4], w_row[4], w_seg[4];
    #pragma unroll
    for (int it = 0; it < 4; it++) {
        int s = tid + it * 256;
        a_row[it] = s >> 3;
        a_seg[it] = (s & 7) * 4;
        w_row[it] = s >> 5;
        w_seg[it] = (s & 31) * 4;
    }

    float c[2][8][4];
    #pragma unroll
    for (int m = 0; m < 2; m++)
        #pragma unroll
        for (int n = 0; n < 8; n++)
            #pragma unroll
            for (int i = 0; i < 4; i++) c[m][n][i] = 0.f;

    // Prefetch chunk 0 into stage 0
    #pragma unroll
    for (int it = 0; it < 4; it++) {
        const int gr = row0 + a_row[it];
        cp_async16(&sm[AS_OFF(0, a_row[it], a_seg[it])],
                   x + (size_t)gr * D + 0 + a_seg[it], gr < M ? 16 : 0);
    }
    #pragma unroll
    for (int it = 0; it < 4; it++) {
        cp_async16(&sm[WS_OFF(0, w_row[it], w_seg[it])],
                   Wm + (size_t)(0 + w_row[it]) * D + w_seg[it], 16);
    }
    cp_async_commit();

    #pragma unroll
    for (int kcc = 0; kcc < 4; kcc++) {
        const int st = kcc & 1;
        if (kcc < 3) {
            const int kn = (kcc + 1) * 32;
            const int sn = st ^ 1;
            #pragma unroll
            for (int it = 0; it < 4; it++) {
                const int gr = row0 + a_row[it];
                cp_async16(&sm[AS_OFF(sn, a_row[it], a_seg[it])],
                           x + (size_t)gr * D + kn + a_seg[it], gr < M ? 16 : 0);
            }
            #pragma unroll
            for (int it = 0; it < 4; it++) {
                cp_async16(&sm[WS_OFF(sn, w_row[it], w_seg[it])],
                           Wm + (size_t)(kn + w_row[it]) * D + w_seg[it], 16);
            }
            cp_async_commit();
            cp_async_wait<1>();
        } else {
            cp_async_wait<0>();
        }
        __syncthreads();

        #pragma unroll
        for (int km = 0; km < 4; km++) {
            const int k8 = km * 8;
            uint32_t a[2][4];
            #pragma unroll
            for (int m = 0; m < 2; m++) {
                const int rb = wm * 32 + m * 16;
                a[m][0] = f2tf32(sm[AS_OFF(st, rb + gID,     k8 + tig    )]);
                a[m][1] = f2tf32(sm[AS_OFF(st, rb + gID + 8, k8 + tig    )]);
                a[m][2] = f2tf32(sm[AS_OFF(st, rb + gID,     k8 + tig + 4)]);
                a[m][3] = f2tf32(sm[AS_OFF(st, rb + gID + 8, k8 + tig + 4)]);
            }
            #pragma unroll
            for (int n = 0; n < 8; n++) {
                const int cb = wn * 64 + n * 8;
                const uint32_t b0 = f2tf32(sm[WS_OFF(st, k8 + tig,     cb + gID)]);
                const uint32_t b1 = f2tf32(sm[WS_OFF(st, k8 + tig + 4, cb + gID)]);
                mma16n8k8(c[0][n], a[0], b0, b1);
                mma16n8k8(c[1][n], a[1], b0, b1);
            }
        }
        __syncthreads();
    }

    // Epilogue: convert to fp16, write half2 pairs
    #pragma unroll
    for (int m = 0; m < 2; m++) {
        const int r0 = row0 + wm * 32 + m * 16 + gID;
        const int r1 = r0 + 8;
        #pragma unroll
        for (int n = 0; n < 8; n++) {
            const int cb = wn * 64 + n * 8 + 2 * tig;
            if (r0 < M)
                *(__half2*)(g_xw + (size_t)r0 * D + cb) =
                    __floats2half2_rn(c[m][n][0], c[m][n][1]);
            if (r1 < M)
                *(__half2*)(g_xw + (size_t)r1 * D + cb) =
                    __floats2half2_rn(c[m][n][2], c[m][n][3]);
        }
    }
}

// ---------------------------------------------------------------------------
// Kernel B: out = A @ xw + bias. One warp per node; TWO edges per LDG.128:
// half-warp h handles edge parity h, lane (q,h) loads dims [8q,8q+8) as uint4.
// Cross-parity shfl.xor(16) reduction at the end; coalesced STG.128 store.
// ---------------------------------------------------------------------------
__global__ void __launch_bounds__(256, 5) spmm_kernel(
    const int*   __restrict__ ecol,   // [E]
    const float* __restrict__ eval,   // [E]
    const float* __restrict__ bias,   // [128]
    float*       __restrict__ out,    // [N, 128]
    int N)
{
    const int warp_in_blk = threadIdx.x >> 5;
    const int lane        = threadIdx.x & 31;
    const int h           = lane >> 4;     // edge parity handled by this half-warp
    const int q           = lane & 15;     // dim group: dims [8q, 8q+8)
    const int node        = blockIdx.x * 8 + warp_in_blk;
    if (node >= N) return;

    const int lo = g_row_ptr[node];
    const int hi = g_row_ptr[node + 1];

    float4 accA = make_float4(0.f, 0.f, 0.f, 0.f);  // dims 8q+0..3
    float4 accB = make_float4(0.f, 0.f, 0.f, 0.f);  // dims 8q+4..7

    for (int base = lo; base < hi; base += 32) {
        const int idx = base + lane;
        int   cc = 0;
        float vv = 0.f;
        if (idx < hi) { cc = ecol[idx]; vv = eval[idx]; }
        const int cnt = min(32, hi - base);

        // batches of 4 edge-pairs (8 edges) for gather MLP
        for (int b = 0; b * 8 < cnt; b++) {
            uint4 kv[4];
            float vj[4];
            #pragma unroll
            for (int u = 0; u < 4; u++) {
                const int p = b * 4 + u;          // pair index (uniform)
                const int j = 2 * p + h;          // edge within 32-block
                const int cj = __shfl_sync(0xffffffffu, cc, j);
                vj[u] = __shfl_sync(0xffffffffu, vv, j);
                if (2 * p < cnt) {
                    kv[u] = *((const uint4*)(g_xw + (size_t)cj * D) + q);
                } else {
                    kv[u] = make_uint4(0u, 0u, 0u, 0u);
                    vj[u] = 0.f;
                }
            }
            #pragma unroll
            for (int u = 0; u < 4; u++) {
                const float2 f0 = __half22float2(*(const __half2*)&kv[u].x);
                const float2 f1 = __half22float2(*(const __half2*)&kv[u].y);
                const float2 f2 = __half22float2(*(const __half2*)&kv[u].z);
                const float2 f3 = __half22float2(*(const __half2*)&kv[u].w);
                accA.x += vj[u] * f0.x;  accA.y += vj[u] * f0.y;
                accA.z += vj[u] * f1.x;  accA.w += vj[u] * f1.y;
                accB.x += vj[u] * f2.x;  accB.y += vj[u] * f2.y;
                accB.z += vj[u] * f3.x;  accB.w += vj[u] * f3.y;
            }
        }
    }

    // Combine even/odd edge partial sums across half-warps
    accA.x += __shfl_xor_sync(0xffffffffu, accA.x, 16);
    accA.y += __shfl_xor_sync(0xffffffffu, accA.y, 16);
    accA.z += __shfl_xor_sync(0xffffffffu, accA.z, 16);
    accA.w += __shfl_xor_sync(0xffffffffu, accA.w, 16);
    accB.x += __shfl_xor_sync(0xffffffffu, accB.x, 16);
    accB.y += __shfl_xor_sync(0xffffffffu, accB.y, 16);
    accB.z += __shfl_xor_sync(0xffffffffu, accB.z, 16);
    accB.w += __shfl_xor_sync(0xffffffffu, accB.w, 16);

    // Lane (q,h) writes dims [8q+4h, 8q+4h+4): fully coalesced 512B per node
    const float4 b4 = ((const float4*)bias)[q * 2 + h];
    float4 r = (h == 0) ? accA : accB;
    r.x += b4.x;  r.y += b4.y;  r.z += b4.z;  r.w += b4.w;
    *(float4*)(out + (size_t)node * D + q * 8 + h * 4) = r;
}

// ---------------------------------------------------------------------------
// Launch
// ---------------------------------------------------------------------------
extern "C" void kernel_launch(void* const* d_in, const int* in_sizes, int n_in,
                              void* d_out, int out_size)
{
    const float* x    = (const float*)d_in[0];   // [N,128]
    const int*   erow = (const int*)  d_in[1];   // [E] sorted
    const int*   ecol = (const int*)  d_in[2];   // [E]
    const float* eval = (const float*)d_in[3];   // [E]
    const float* Wm   = (const float*)d_in[4];   // [128,128]
    const float* bias = (const float*)d_in[5];   // [128]
    float*       out  = (float*)d_out;

    const int N = out_size / D;
    const int E = in_sizes[1];

    const int G1 = (N + 127) / 128;              // gemm blocks
    const int G2 = (E + 4095) / 4096;            // row_ptr blocks (16 edges/thread)
    const int smem_bytes = SMEM_FLOATS * 4;      // ~71.7 KB

    cudaFuncSetAttribute(fused_gemm_rowptr_kernel,
                         cudaFuncAttributeMaxDynamicSharedMemorySize, smem_bytes);

    // Kernel A: fused GEMM + row_ptr (independent block families, one launch)
    fused_gemm_rowptr_kernel<<<G1 + G2, 256, smem_bytes>>>(x, Wm, erow, N, N, E, G1);

    // Kernel B: out = A @ xw + bias
    spmm_kernel<<<(N + 7) / 8, 256>>>(ecol, eval, bias, out, N);
}

// round 13
// speedup vs baseline: 1.1401x; 1.1401x over previous
#include <cuda_runtime.h>
#include <cuda_fp16.h>
#include <cuda_bf16.h>
#include <cstdint>

// ---------------------------------------------------------------------------
// GCN layer, reordered:  out = A @ (x @ W) + bias
//   Kernel A (fused): blocks [0,G1)  : xw = x @ W  (tf32 mma, cp.async 2-stage,
//                                      fp32 accum, fp16 store)
//                     blocks [G1,..) : CSR row_ptr from sorted COO rows
//   Kernel B: out = A @ xw + bias    (CSR SpMM, warp/node; smem edge staging,
//                                     2 edges/LDG.128, packed f32x2 FFMA)
// ---------------------------------------------------------------------------

#define D 128
#define MAX_NODES 100000

typedef unsigned long long u64;

__device__ __half g_xw[(size_t)MAX_NODES * D];   // fp16: halves gather traffic
__device__ int    g_row_ptr[MAX_NODES + 1];

__device__ __forceinline__ uint32_t f2tf32(float f) {
    uint32_t r;
    asm("cvt.rna.tf32.f32 %0, %1;" : "=r"(r) : "f"(f));
    return r;
}

__device__ __forceinline__ void mma16n8k8(float* c, const uint32_t* a,
                                          uint32_t b0, uint32_t b1) {
    asm volatile(
        "mma.sync.aligned.m16n8k8.row.col.f32.tf32.tf32.f32 "
        "{%0,%1,%2,%3}, {%4,%5,%6,%7}, {%8,%9}, {%0,%1,%2,%3};"
        : "+f"(c[0]), "+f"(c[1]), "+f"(c[2]), "+f"(c[3])
        : "r"(a[0]), "r"(a[1]), "r"(a[2]), "r"(a[3]), "r"(b0), "r"(b1));
}

__device__ __forceinline__ void cp_async16(void* smem_dst, const void* gsrc, int src_bytes) {
    uint32_t sa = (uint32_t)__cvta_generic_to_shared(smem_dst);
    asm volatile("cp.async.cg.shared.global [%0], [%1], 16, %2;\n"
                 :: "r"(sa), "l"(gsrc), "r"(src_bytes));
}
__device__ __forceinline__ void cp_async_commit() {
    asm volatile("cp.async.commit_group;\n");
}
template <int NG>
__device__ __forceinline__ void cp_async_wait() {
    asm volatile("cp.async.wait_group %0;\n" :: "n"(NG));
}

// ---- packed f32x2 helpers (FFMA2 path, sm_103a) ----
__device__ __forceinline__ u64 pack_f32x2(float lo, float hi) {
    u64 r;
    asm("mov.b64 %0, {%1, %2};" : "=l"(r) : "f"(lo), "f"(hi));
    return r;
}
__device__ __forceinline__ void unpack_f32x2(u64 v, float& lo, float& hi) {
    asm("mov.b64 {%0, %1}, %2;" : "=f"(lo), "=f"(hi) : "l"(v));
}
__device__ __forceinline__ u64 ffma2(u64 a, u64 b, u64 c) {
    u64 d;
    asm("fma.rn.f32x2 %0, %1, %2, %3;" : "=l"(d) : "l"(a), "l"(b), "l"(c));
    return d;
}
__device__ __forceinline__ u64 h2f2(uint32_t h2bits) {
    __half2 h = *(const __half2*)&h2bits;
    float2 f = __half22float2(h);
    return pack_f32x2(f.x, f.y);
}

// Dynamic smem layout (floats):
//   AS(st, r, c) : 2 x [128][36]  at offset st*4608 + r*36 + c
//   WS(st, r, c) : 2 x [32][136]  at offset 9216 + st*4352 + r*136 + c
#define AS_OFF(st, r, c) ((st) * 4608 + (r) * 36 + (c))
#define WS_OFF(st, r, c) (9216 + (st) * 4352 + (r) * 136 + (c))
#define SMEM_FLOATS (9216 + 2 * 4352)

// ---------------------------------------------------------------------------
// Fused kernel: GEMM blocks + row_ptr blocks (independent work, one launch)
// ---------------------------------------------------------------------------
__global__ void __launch_bounds__(256) fused_gemm_rowptr_kernel(
    const float* __restrict__ x,     // [M, 128]
    const float* __restrict__ Wm,    // [128, 128]
    const int*   __restrict__ erow,  // [E] sorted
    int M, int N, int E, int G1)
{
    extern __shared__ float sm[];
    const int tid = threadIdx.x;

    if (blockIdx.x >= G1) {
        // ----- row_ptr part: 16 edges per thread (4x int4) -----
        const int t    = (blockIdx.x - G1) * 256 + tid;
        const int base = t * 16;
        if (base >= E) return;

        int v[17];
        v[0] = (base == 0) ? -1 : erow[base - 1];

        const int cnt = min(16, E - base);
        if (cnt == 16) {
            #pragma unroll
            for (int q = 0; q < 4; q++) {
                const int4 a = *(const int4*)(erow + base + q * 4);
                v[q * 4 + 1] = a.x; v[q * 4 + 2] = a.y;
                v[q * 4 + 3] = a.z; v[q * 4 + 4] = a.w;
            }
        } else {
            for (int k = 0; k < cnt; k++) v[k + 1] = erow[base + k];
        }

        #pragma unroll
        for (int k = 1; k <= 16; k++) {
            if (k <= cnt) {
                for (int r = v[k - 1] + 1; r <= v[k]; r++)
                    g_row_ptr[r] = base + k - 1;
            }
        }
        if (base + cnt == E) {
            for (int r = v[cnt] + 1; r <= N; r++) g_row_ptr[r] = E;
        }
        return;
    }

    // ----- GEMM part: 128x128 tile, 2-stage cp.async pipeline -----
    const int lane = tid & 31;
    const int wid  = tid >> 5;
    const int wm   = wid & 3;
    const int wn   = wid >> 2;
    const int row0 = blockIdx.x * 128;

    const int gID = lane >> 2;
    const int tig = lane & 3;

    int a_row[4], a_seg[4], w_row[4], w_seg[4];
    #pragma unroll
    for (int it = 0; it < 4; it++) {
        int s = tid + it * 256;
        a_row[it] = s >> 3;
        a_seg[it] = (s & 7) * 4;
        w_row[it] = s >> 5;
        w_seg[it] = (s & 31) * 4;
    }

    float c[2][8][4];
    #pragma unroll
    for (int m = 0; m < 2; m++)
        #pragma unroll
        for (int n = 0; n < 8; n++)
            #pragma unroll
            for (int i = 0; i < 4; i++) c[m][n][i] = 0.f;

    // Prefetch chunk 0 into stage 0
    #pragma unroll
    for (int it = 0; it < 4; it++) {
        const int gr = row0 + a_row[it];
        cp_async16(&sm[AS_OFF(0, a_row[it], a_seg[it])],
                   x + (size_t)gr * D + 0 + a_seg[it], gr < M ? 16 : 0);
    }
    #pragma unroll
    for (int it = 0; it < 4; it++) {
        cp_async16(&sm[WS_OFF(0, w_row[it], w_seg[it])],
                   Wm + (size_t)(0 + w_row[it]) * D + w_seg[it], 16);
    }
    cp_async_commit();

    #pragma unroll
    for (int kcc = 0; kcc < 4; kcc++) {
        const int st = kcc & 1;
        if (kcc < 3) {
            const int kn = (kcc + 1) * 32;
            const int sn = st ^ 1;
            #pragma unroll
            for (int it = 0; it < 4; it++) {
                const int gr = row0 + a_row[it];
                cp_async16(&sm[AS_OFF(sn, a_row[it], a_seg[it])],
                           x + (size_t)gr * D + kn + a_seg[it], gr < M ? 16 : 0);
            }
            #pragma unroll
            for (int it = 0; it < 4; it++) {
                cp_async16(&sm[WS_OFF(sn, w_row[it], w_seg[it])],
                           Wm + (size_t)(kn + w_row[it]) * D + w_seg[it], 16);
            }
            cp_async_commit();
            cp_async_wait<1>();
        } else {
            cp_async_wait<0>();
        }
        __syncthreads();

        #pragma unroll
        for (int km = 0; km < 4; km++) {
            const int k8 = km * 8;
            uint32_t a[2][4];
            #pragma unroll
            for (int m = 0; m < 2; m++) {
                const int rb = wm * 32 + m * 16;
                a[m][0] = f2tf32(sm[AS_OFF(st, rb + gID,     k8 + tig    )]);
                a[m][1] = f2tf32(sm[AS_OFF(st, rb + gID + 8, k8 + tig    )]);
                a[m][2] = f2tf32(sm[AS_OFF(st, rb + gID,     k8 + tig + 4)]);
                a[m][3] = f2tf32(sm[AS_OFF(st, rb + gID + 8, k8 + tig + 4)]);
            }
            #pragma unroll
            for (int n = 0; n < 8; n++) {
                const int cb = wn * 64 + n * 8;
                const uint32_t b0 = f2tf32(sm[WS_OFF(st, k8 + tig,     cb + gID)]);
                const uint32_t b1 = f2tf32(sm[WS_OFF(st, k8 + tig + 4, cb + gID)]);
                mma16n8k8(c[0][n], a[0], b0, b1);
                mma16n8k8(c[1][n], a[1], b0, b1);
            }
        }
        __syncthreads();
    }

    // Epilogue: convert to fp16, write half2 pairs
    #pragma unroll
    for (int m = 0; m < 2; m++) {
        const int r0 = row0 + wm * 32 + m * 16 + gID;
        const int r1 = r0 + 8;
        #pragma unroll
        for (int n = 0; n < 8; n++) {
            const int cb = wn * 64 + n * 8 + 2 * tig;
            if (r0 < M)
                *(__half2*)(g_xw + (size_t)r0 * D + cb) =
                    __floats2half2_rn(c[m][n][0], c[m][n][1]);
            if (r1 < M)
                *(__half2*)(g_xw + (size_t)r1 * D + cb) =
                    __floats2half2_rn(c[m][n][2], c[m][n][3]);
        }
    }
}

// ---------------------------------------------------------------------------
// Kernel B: out = A @ xw + bias. One warp per node. Edge (col,val) staged in
// smem (LDS.64 broadcast instead of SHFL pairs); two edges per LDG.128
// (half-warp h = edge parity, lane q owns dims [8q,8q+8)); packed f32x2 FFMA.
// ---------------------------------------------------------------------------
__global__ void __launch_bounds__(256, 4) spmm_kernel(
    const int*   __restrict__ ecol,   // [E]
    const float* __restrict__ eval,   // [E]
    const float* __restrict__ bias,   // [128]
    float*       __restrict__ out,    // [N, 128]
    int N)
{
    __shared__ int2 s_edges[8][2][32];    // [warp][buf][edge] = (col, val bits)

    const int w    = threadIdx.x >> 5;
    const int lane = threadIdx.x & 31;
    const int h    = lane >> 4;           // edge parity handled by this half-warp
    const int q    = lane & 15;           // dim group: dims [8q, 8q+8)
    const int node = blockIdx.x * 8 + w;
    if (node >= N) return;

    const int lo = g_row_ptr[node];
    const int hi = g_row_ptr[node + 1];

    // f32x2 accumulators: acc0 = dims (8q+0,8q+1) ... acc3 = dims (8q+6,8q+7)
    u64 acc0 = 0ull, acc1 = 0ull, acc2 = 0ull, acc3 = 0ull;

    // Stage block 0 (invalid lanes hold zeros -> harmless 0-weighted gathers)
    int   cc = 0;
    float vv = 0.f;
    {
        const int idx = lo + lane;
        if (idx < hi) { cc = ecol[idx]; vv = eval[idx]; }
    }

    int buf = 0;
    for (int base = lo; base < hi; base += 32) {
        s_edges[w][buf][lane] = make_int2(cc, __float_as_int(vv));
        __syncwarp();

        // Prefetch next block's staging (coalesced; latency hidden by compute)
        cc = 0; vv = 0.f;
        {
            const int idx = base + 32 + lane;
            if (idx < hi) { cc = ecol[idx]; vv = eval[idx]; }
        }

        const int cnt = min(32, hi - base);
        for (int pb = 0; 2 * pb < cnt; pb += 4) {
            uint4 kv[4];
            u64   vj2[4];
            #pragma unroll
            for (int u = 0; u < 4; u++) {
                const int2 e = s_edges[w][buf][2 * (pb + u) + h];
                const float vjf = __int_as_float(e.y);
                vj2[u] = pack_f32x2(vjf, vjf);
                kv[u]  = *((const uint4*)(g_xw + (size_t)e.x * D) + q);
            }
            #pragma unroll
            for (int u = 0; u < 4; u++) {
                acc0 = ffma2(h2f2(kv[u].x), vj2[u], acc0);
                acc1 = ffma2(h2f2(kv[u].y), vj2[u], acc1);
                acc2 = ffma2(h2f2(kv[u].z), vj2[u], acc2);
                acc3 = ffma2(h2f2(kv[u].w), vj2[u], acc3);
            }
        }
        buf ^= 1;
    }

    // Unpack to scalars: accA = dims 8q..8q+3, accB = dims 8q+4..8q+7
    float4 accA, accB;
    unpack_f32x2(acc0, accA.x, accA.y);
    unpack_f32x2(acc1, accA.z, accA.w);
    unpack_f32x2(acc2, accB.x, accB.y);
    unpack_f32x2(acc3, accB.z, accB.w);

    // Combine even/odd edge partial sums across half-warps
    accA.x += __shfl_xor_sync(0xffffffffu, accA.x, 16);
    accA.y += __shfl_xor_sync(0xffffffffu, accA.y, 16);
    accA.z += __shfl_xor_sync(0xffffffffu, accA.z, 16);
    accA.w += __shfl_xor_sync(0xffffffffu, accA.w, 16);
    accB.x += __shfl_xor_sync(0xffffffffu, accB.x, 16);
    accB.y += __shfl_xor_sync(0xffffffffu, accB.y, 16);
    accB.z += __shfl_xor_sync(0xffffffffu, accB.z, 16);
    accB.w += __shfl_xor_sync(0xffffffffu, accB.w, 16);

    // Lane (q,h) writes dims [8q+4h, 8q+4h+4): fully coalesced 512B per node
    const float4 b4 = ((const float4*)bias)[q * 2 + h];
    float4 r = (h == 0) ? accA : accB;
    r.x += b4.x;  r.y += b4.y;  r.z += b4.z;  r.w += b4.w;
    *(float4*)(out + (size_t)node * D + q * 8 + h * 4) = r;
}

// ---------------------------------------------------------------------------
// Launch
// ---------------------------------------------------------------------------
extern "C" void kernel_launch(void* const* d_in, const int* in_sizes, int n_in,
                              void* d_out, int out_size)
{
    const float* x    = (const float*)d_in[0];   // [N,128]
    const int*   erow = (const int*)  d_in[1];   // [E] sorted
    const int*   ecol = (const int*)  d_in[2];   // [E]
    const float* eval = (const float*)d_in[3];   // [E]
    const float* Wm   = (const float*)d_in[4];   // [128,128]
    const float* bias = (const float*)d_in[5];   // [128]
    float*       out  = (float*)d_out;

    const int N = out_size / D;
    const int E = in_sizes[1];

    const int G1 = (N + 127) / 128;              // gemm blocks
    const int G2 = (E + 4095) / 4096;            // row_ptr blocks (16 edges/thread)
    const int smem_bytes = SMEM_FLOATS * 4;      // ~71.7 KB

    cudaFuncSetAttribute(fused_gemm_rowptr_kernel,
                         cudaFuncAttributeMaxDynamicSharedMemorySize, smem_bytes);

    // Kernel A: fused GEMM + row_ptr (independent block families, one launch)
    fused_gemm_rowptr_kernel<<<G1 + G2, 256, smem_bytes>>>(x, Wm, erow, N, N, E, G1);

    // Kernel B: out = A @ xw + bias
    spmm_kernel<<<(N + 7) / 8, 256>>>(ecol, eval, bias, out, N);
}